// round 15
// baseline (speedup 1.0000x reference)
#include <cuda_runtime.h>

#define NG 21
#define NTRIP 69

typedef unsigned long long ull;

struct Meta {
    const float* f[6];
    const float* w[6];
    float*       out;
    int cg_off[NG][6];
    int col_base[NG][6];
    int trip_l1[NTRIP];
    int trip_l2[NTRIP];
    int trip_l[NTRIP];
    int trip_off[NTRIP];
};

__device__ float d_cg[4096];
__device__ float d_wt[565248];   // planar weights: [0,282624) real, [282624,565248) imag

#define WPLANE 282624
#define NCG 4066

__constant__ int c_NUMCOLS[6] = {1536, 2560, 3328, 3584, 3584, 3072};
__constant__ int c_FOFF[7]    = {0, 32, 128, 288, 512, 800, 1152};
__constant__ int c_OUTOFF[6]  = {0, 8192, 32768, 73728, 131072, 204800};
__constant__ int c_WTP[7] = {0, 24576, 65536, 118784, 176128, 233472, 282624};

__constant__ double c_fact[17] = {
    1.0, 1.0, 2.0, 6.0, 24.0, 120.0, 720.0, 5040.0, 40320.0, 362880.0,
    3628800.0, 39916800.0, 479001600.0, 6227020800.0, 87178291200.0,
    1307674368000.0, 20922789888000.0
};

// ---- packed f32x2 helpers -------------------------------------------------
__device__ __forceinline__ ull ffma2(ull a, ull b, ull c) {
    ull d; asm("fma.rn.f32x2 %0, %1, %2, %3;" : "=l"(d) : "l"(a), "l"(b), "l"(c)); return d;
}
__device__ __forceinline__ float2 upk(ull a) {
    float2 r; asm("mov.b64 {%0,%1}, %2;" : "=f"(r.x), "=f"(r.y) : "l"(a)); return r;
}
#define SGN2 0x8000000080000000ULL

// ---------------------------------------------------------------------------
// Setup kernel: CG coefficients + planar weight transpose (merged)
// ---------------------------------------------------------------------------
__device__ double cg_coeff_d(int l1, int l2, int l, int m1, int m2, int m) {
    double pref = sqrt((2.0 * l + 1.0) * c_fact[l + l1 - l2] * c_fact[l - l1 + l2] *
                       c_fact[l1 + l2 - l] / c_fact[l1 + l2 + l + 1]);
    pref *= sqrt(c_fact[l + m] * c_fact[l - m] * c_fact[l1 - m1] * c_fact[l1 + m1] *
                 c_fact[l2 - m2] * c_fact[l2 + m2]);
    int kmin = 0;
    if (l2 - l - m1 > kmin) kmin = l2 - l - m1;
    if (l1 + m2 - l > kmin) kmin = l1 + m2 - l;
    int kmax = l1 + l2 - l;
    if (l1 - m1 < kmax) kmax = l1 - m1;
    if (l2 + m2 < kmax) kmax = l2 + m2;
    double s = 0.0;
    for (int k = kmin; k <= kmax; k++) {
        double d = c_fact[k] * c_fact[l1 + l2 - l - k] * c_fact[l1 - m1 - k] *
                   c_fact[l2 + m2 - k] * c_fact[l - l2 + m1 + k] * c_fact[l - l1 - m2 + k];
        s += ((k & 1) ? -1.0 : 1.0) / d;
    }
    return pref * s;
}

__global__ void setup_kernel(Meta meta) {
    if (blockIdx.x < NTRIP) {
        int tr = blockIdx.x;
        int l1 = meta.trip_l1[tr], l2 = meta.trip_l2[tr], l = meta.trip_l[tr];
        int off = meta.trip_off[tr];
        int n1 = 2 * l1 + 1, n2 = 2 * l2 + 1;
        int idx = threadIdx.x;
        if (idx >= n1 * n2) return;
        int m1i = idx / n2, m2i = idx % n2;
        int m1 = m1i - l1, m2 = m2i - l2, m = m1 + m2;
        float c = 0.0f;
        if (m >= -l && m <= l)
            c = (float)cg_coeff_d(l1, l2, l, m1, m2, m);
        d_cg[off + idx] = c;
    } else {
        int j = (blockIdx.x - NTRIP) * blockDim.x + threadIdx.x;
        if (j >= 565248) return;
        int plane = (j >= WPLANE) ? 1 : 0;
        int r0 = j - plane * WPLANE;
        int l = 0;
#pragma unroll
        for (int ll = 1; ll < 6; ll++)
            if (r0 >= c_WTP[ll]) l = ll;
        int r = r0 - c_WTP[l];
        int j3 = r & 3;
        int t = (r >> 2) & 15;
        int c4 = r >> 6;
        int c = c4 * 4 + j3;
        d_wt[j] = meta.w[l][(t * c_NUMCOLS[l] + c) * 2 + plane];
    }
}

// ---------------------------------------------------------------------------
// Stage-2 inner accumulation: 2 accumulator families (real via sign-flipped
// wi). CNT=5 merges the even-l leftover row into its last quad (no cnt-1
// straggler loops). Unroll 2 on the CNT5 path to bound register pressure.
// ---------------------------------------------------------------------------
template <int CNT>
__device__ __forceinline__ void s2_acc(const ulonglong2* __restrict__ wr,
                                       const ulonglong2* __restrict__ wi,
                                       const ulonglong2* __restrict__ fr,
                                       const ulonglong2* __restrict__ fi,
                                       int len, int ooff, float* out_s)
{
    ull A[CNT], C[CNT];
#pragma unroll
    for (int q = 0; q < CNT; q++) { A[q] = 0; C[q] = 0; }
    if constexpr (CNT >= 5) {
#pragma unroll 2
        for (int p = 0; p < len; p++) {
            ulonglong2 w_r = wr[p * 16];
            ulonglong2 w_i = wi[p * 16];
            ull wnx = w_i.x ^ SGN2, wny = w_i.y ^ SGN2;
#pragma unroll
            for (int q = 0; q < CNT; q++) {
                ulonglong2 f_r = fr[q * 64 + p];
                ulonglong2 f_i = fi[q * 64 + p];
                A[q] = ffma2(w_r.x, f_r.x, A[q]);
                A[q] = ffma2(w_r.y, f_r.y, A[q]);
                A[q] = ffma2(wnx,   f_i.x, A[q]);
                A[q] = ffma2(wny,   f_i.y, A[q]);
                C[q] = ffma2(w_r.x, f_i.x, C[q]);
                C[q] = ffma2(w_r.y, f_i.y, C[q]);
                C[q] = ffma2(w_i.x, f_r.x, C[q]);
                C[q] = ffma2(w_i.y, f_r.y, C[q]);
            }
        }
    } else {
#pragma unroll 4
        for (int p = 0; p < len; p++) {
            ulonglong2 w_r = wr[p * 16];
            ulonglong2 w_i = wi[p * 16];
            ull wnx = w_i.x ^ SGN2, wny = w_i.y ^ SGN2;
#pragma unroll
            for (int q = 0; q < CNT; q++) {
                ulonglong2 f_r = fr[q * 64 + p];
                ulonglong2 f_i = fi[q * 64 + p];
                A[q] = ffma2(w_r.x, f_r.x, A[q]);
                A[q] = ffma2(w_r.y, f_r.y, A[q]);
                A[q] = ffma2(wnx,   f_i.x, A[q]);
                A[q] = ffma2(wny,   f_i.y, A[q]);
                C[q] = ffma2(w_r.x, f_i.x, C[q]);
                C[q] = ffma2(w_r.y, f_i.y, C[q]);
                C[q] = ffma2(w_i.x, f_r.x, C[q]);
                C[q] = ffma2(w_i.y, f_r.y, C[q]);
            }
        }
    }
#pragma unroll
    for (int q = 0; q < CNT; q++) {
        float2 a2 = upk(A[q]), c2 = upk(C[q]);
        atomicAdd(&out_s[ooff + 2 * q],     a2.x + a2.y);
        atomicAdd(&out_s[ooff + 2 * q + 1], c2.x + c2.y);
    }
}

// ---------------------------------------------------------------------------
// Stage-2 with in-thread entry decode, class-sorted: cnt4, cnt5, cnt3, cnt1.
// Per l: odd l -> (l-1)/2 cnt4 + 1 cnt3;  even l>=2 -> (l/2-1) cnt4 + 1 cnt5;
// l==0 -> 1 cnt1.
// ---------------------------------------------------------------------------
__device__ __noinline__ void stage2(int E, int LA, int LB, int lcs,
                                    const int* colbase6,
                                    const float* frag_r, const float* frag_i,
                                    float* out_s, int tid)
{
    int csplit = 1 << lcs;
    int cmask = csplit - 1;
    int len = 64 >> lcs;
    int N4 = 0, N5 = 0, N3 = 0;
    for (int l = LA; l <= LB; l++) {
        if (l & 1) { N3++; N4 += (l - 1) >> 1; }
        else if (l >= 2) { N5++; N4 += (l >> 1) - 1; }
    }
    int U4e = N4 * csplit, U5e = N5 * csplit, U3e = N3 * csplit;
    int LA2 = LA * LA;
    int fe = (LA <= 2) ? 2 : (LA + (LA & 1));   // first even l>=2 in range
    int fo = LA | 1;                            // first odd l in range
    for (int e = tid; e < E; e += 256) {
        int t = e & 15;
        int u = e >> 4;
        int l, k0, cnt, ch;
        if (u < U4e) {
            int q = u >> lcs; ch = u & cmask;
            l = LA;
            for (;;) {
                int n4 = (l & 1) ? ((l - 1) >> 1) : ((l >= 2) ? (l >> 1) - 1 : 0);
                if (q < n4) break;
                q -= n4; l++;
            }
            k0 = q * 4; cnt = 4;
        } else if (u < U4e + U5e) {
            int idx = u - U4e;
            int j = idx >> lcs; ch = idx & cmask;
            l = fe + 2 * j;
            k0 = 2 * l - 4; cnt = 5;
        } else if (u < U4e + U5e + U3e) {
            int idx = u - U4e - U5e;
            int j = idx >> lcs; ch = idx & cmask;
            l = fo + 2 * j;
            k0 = 2 * l - 2; cnt = 3;
        } else {
            ch = (u - U4e - U5e - U3e) & cmask;
            l = 0; k0 = 0; cnt = 1;
        }
        int pstart = ch * len;
        int woff = c_WTP[l] + ((colbase6[l] >> 2) + pstart) * 64 + t * 4;
        int kk0 = (l * l - LA2) + k0;
        int ooff = c_FOFF[l] + (t * (2 * l + 1) + k0) * 2;
        const ulonglong2* wr = (const ulonglong2*)(d_wt + woff);
        const ulonglong2* wi = (const ulonglong2*)(d_wt + WPLANE + woff);
        const ulonglong2* fr = (const ulonglong2*)frag_r + kk0 * 64 + pstart;
        const ulonglong2* fi = (const ulonglong2*)frag_i + kk0 * 64 + pstart;
        if (cnt == 4)      s2_acc<4>(wr, wi, fr, fi, len, ooff, out_s);
        else if (cnt == 5) s2_acc<5>(wr, wi, fr, fi, len, ooff, out_s);
        else if (cnt == 3) s2_acc<3>(wr, wi, fr, fi, len, ooff, out_s);
        else               s2_acc<1>(wr, wi, fr, fi, len, ooff, out_s);
    }
}

// ---- cost-optimal c-split: minimize max-thread rounds * (len + overhead) ---
__host__ __device__ constexpr int s2cost(int E0, int L) {
    return (((E0 << L) + 255) / 256) * ((64 >> L) + 2);
}
__host__ __device__ constexpr int bestlcs(int E0) {
    int best = 0, bc = s2cost(E0, 0);
    for (int L = 1; L <= 4; L++) {
        int c = s2cost(E0, L);
        if (c < bc) { bc = c; best = L; }
    }
    return best;
}
// quads per l under the new decomposition
__host__ __device__ constexpr int nq_new(int l) {
    return (l == 0) ? 1 : ((l & 1) ? ((l + 1) / 2) : (l / 2));
}

// ---------------------------------------------------------------------------
// Main fused kernel: one CTA per batch element (champion structure).
// ---------------------------------------------------------------------------
template <int L1, int L2, int LA, int LB>
__device__ __forceinline__ void process_range(
    int g, const Meta& meta, float* __restrict__ f_s, float* __restrict__ out_s,
    const float* __restrict__ cg_a,
    float* __restrict__ frag_r, float* __restrict__ frag_i, int tid)
{
    constexpr int N1 = 2 * L1 + 1;
    constexpr int N2 = 2 * L2 + 1;
    constexpr int STRIDE = N1 * N2;
    constexpr int SK = (LB + 1) * (LB + 1) - LA * LA;
    static_assert(SK <= 21, "frag rows");
    constexpr int KQ =
        (((LA + 0) <= LB) ? nq_new(LA + 0) : 0) +
        (((LA + 1) <= LB) ? nq_new(LA + 1) : 0) +
        (((LA + 2) <= LB) ? nq_new(LA + 2) : 0) +
        (((LA + 3) <= LB) ? nq_new(LA + 3) : 0) +
        (((LA + 4) <= LB) ? nq_new(LA + 4) : 0) +
        (((LA + 5) <= LB) ? nq_new(LA + 5) : 0);
    constexpr int E0 = 16 * KQ;
    constexpr int LCS = bestlcs(E0);
    constexpr int E = E0 << LCS;

    __syncthreads();  // prior stage2 done reading frag

    // ---- stage 1: CG fragments, thread = (i,j) channel pair = column ----
    {
        int i = tid >> 4, j = tid & 15;
        float accr[SK], acci[SK];
#pragma unroll
        for (int q = 0; q < SK; q++) { accr[q] = 0.0f; acci[q] = 0.0f; }
        const float* cgsub = cg_a + meta.cg_off[g][LA];
        const float* f1 = f_s + c_FOFF[L1] + i * N1 * 2;
        const float* f2 = f_s + c_FOFF[L2] + j * N2 * 2;
#pragma unroll
        for (int m1 = 0; m1 < N1; m1++) {
            float ar = f1[2 * m1], ai = f1[2 * m1 + 1];
#pragma unroll
            for (int m2 = 0; m2 < N2; m2++) {
                float br = f2[2 * m2], bi = f2[2 * m2 + 1];
                float pr = ar * br - ai * bi;
                float pi = ar * bi + ai * br;
                int m = m1 + m2 - L1 - L2;
#pragma unroll
                for (int l = LA; l <= LB; l++) {
                    if (m >= -l && m <= l) {
                        float c = cgsub[(l - LA) * STRIDE + m1 * N2 + m2];
                        int kk = (l * l - LA * LA) + m + l;
                        accr[kk] += c * pr;
                        acci[kk] += c * pi;
                    }
                }
            }
        }
#pragma unroll
        for (int q = 0; q < SK; q++) {
            frag_r[q * 256 + tid] = accr[q];
            frag_i[q * 256 + tid] = acci[q];
        }
    }
    __syncthreads();  // fragments ready

    stage2(E, LA, LB, LCS, meta.col_base[g], frag_r, frag_i, out_s, tid);
}

__global__ void __launch_bounds__(256, 2) uf_kernel(Meta meta) {
    extern __shared__ float smem[];
    float* f_s    = smem;                 // 1152
    float* out_s  = smem + 1152;          // 1152
    float* cg_a   = smem + 2304;          // 4096 (4066 used), resident CG table
    float* frag_r = smem + 6400;          // 5376 (21 rows * 256), 16B-aligned
    float* frag_i = smem + 11776;         // 5376   total 17152 words = 68608 B

    int tid = threadIdx.x;
    int b = blockIdx.x;

#pragma unroll
    for (int l = 0; l < 6; l++) {
        int n = 32 * (2 * l + 1);
        const float* src = meta.f[l] + b * n;
        for (int s = tid; s < n; s += 256) f_s[c_FOFF[l] + s] = src[s];
    }
    for (int s = tid; s < 1152; s += 256) out_s[s] = 0.0f;
    for (int s = tid; s < NCG; s += 256) cg_a[s] = d_cg[s];

#define PG(A, B2, G, LA, LB) \
    process_range<A, B2, LA, LB>(G, meta, f_s, out_s, cg_a, frag_r, frag_i, tid)
    PG(0, 0, 0, 0, 0);
    PG(1, 0, 1, 1, 1);
    PG(1, 1, 2, 0, 2);
    PG(2, 0, 3, 2, 2);
    PG(2, 1, 4, 1, 3);
    PG(2, 2, 5, 0, 3);  PG(2, 2, 5, 4, 4);
    PG(3, 0, 6, 3, 3);
    PG(3, 1, 7, 2, 4);
    PG(3, 2, 8, 1, 3);  PG(3, 2, 8, 4, 5);
    PG(3, 3, 9, 0, 3);  PG(3, 3, 9, 4, 5);
    PG(4, 0, 10, 4, 4);
    PG(4, 1, 11, 3, 4); PG(4, 1, 11, 5, 5);
    PG(4, 2, 12, 2, 4); PG(4, 2, 12, 5, 5);
    PG(4, 3, 13, 1, 3); PG(4, 3, 13, 4, 5);
    PG(4, 4, 14, 0, 3); PG(4, 4, 14, 4, 5);
    PG(5, 0, 15, 5, 5);
    PG(5, 1, 16, 4, 5);
    PG(5, 2, 17, 3, 4); PG(5, 2, 17, 5, 5);
    PG(5, 3, 18, 2, 4); PG(5, 3, 18, 5, 5);
    PG(5, 4, 19, 1, 3); PG(5, 4, 19, 4, 5);
    PG(5, 5, 20, 0, 3); PG(5, 5, 20, 4, 5);
#undef PG

    __syncthreads();
    for (int s = tid; s < 1152; s += 256) {
        int l = 0;
#pragma unroll
        for (int ll = 1; ll < 6; ll++)
            if (s >= c_FOFF[ll]) l = ll;
        int rel = s - c_FOFF[l];
        meta.out[c_OUTOFF[l] + b * 32 * (2 * l + 1) + rel] = out_s[s];
    }
}

// ---------------------------------------------------------------------------
// Host launch
// ---------------------------------------------------------------------------
extern "C" void kernel_launch(void* const* d_in, const int* in_sizes, int n_in,
                              void* d_out, int out_size) {
    Meta m;
    const int fsz[6] = {8192, 24576, 40960, 57344, 73728, 90112};
    const int wsz[6] = {49152, 81920, 106496, 114688, 114688, 98304};
    bool used[64];
    for (int i = 0; i < 64; i++) used[i] = false;
    for (int l = 0; l < 6; l++) {
        for (int idx = 0; idx < n_in; idx++) {
            if (!used[idx] && in_sizes[idx] == fsz[l]) {
                m.f[l] = (const float*)d_in[idx];
                used[idx] = true;
                break;
            }
        }
    }
    for (int l = 0; l < 6; l++) {
        for (int idx = 0; idx < n_in; idx++) {
            if (!used[idx] && in_sizes[idx] == wsz[l]) {
                m.w[l] = (const float*)d_in[idx];
                used[idx] = true;
                break;
            }
        }
    }
    m.out = (float*)d_out;

    int off = 0, g = 0, tr = 0;
    int cnt[6] = {0, 0, 0, 0, 0, 0};
    for (int l1 = 0; l1 <= 5; l1++) {
        for (int l2 = 0; l2 <= l1; l2++) {
            int lmin = l1 - l2;
            int lmax = (l1 + l2 < 5) ? (l1 + l2) : 5;
            for (int l = lmin; l <= lmax; l++) {
                m.cg_off[g][l] = off;
                m.trip_l1[tr] = l1;
                m.trip_l2[tr] = l2;
                m.trip_l[tr]  = l;
                m.trip_off[tr] = off;
                tr++;
                off += (2 * l1 + 1) * (2 * l2 + 1);
                m.col_base[g][l] = cnt[l] * 256;
                cnt[l]++;
            }
            g++;
        }
    }

    const int SMEM_BYTES = 17152 * 4;  // 68608
    cudaFuncSetAttribute(uf_kernel, cudaFuncAttributeMaxDynamicSharedMemorySize, SMEM_BYTES);

    setup_kernel<<<NTRIP + (565248 + 127) / 128, 128>>>(m);
    uf_kernel<<<256, 256, SMEM_BYTES>>>(m);
}

// round 16
// speedup vs baseline: 1.0418x; 1.0418x over previous
#include <cuda_runtime.h>

#define NG 21
#define NTRIP 69
#define NTILE 138

typedef unsigned long long ull;

struct Meta {
    const float* f[6];
    const float* w[6];
    float*       out;
    int cg_off[NG][6];
    int col_base[NG][6];
    int trip_l1[NTRIP];
    int trip_l2[NTRIP];
    int trip_l[NTRIP];
    int trip_off[NTRIP];
};

__device__ float d_cg[4096];
__device__ float d_wt[565248];   // planar weights: [0,282624) real, [282624,565248) imag

#define WPLANE 282624
#define NCG 4066

__constant__ int c_NUMCOLS[6] = {1536, 2560, 3328, 3584, 3584, 3072};
__constant__ int c_FOFF[7]    = {0, 32, 128, 288, 512, 800, 1152};
__constant__ int c_OUTOFF[6]  = {0, 8192, 32768, 73728, 131072, 204800};
__constant__ int c_WTP[7] = {0, 24576, 65536, 118784, 176128, 233472, 282624};
// cumulative 128-column transpose tiles per l: NUMCOLS/128 = {12,20,26,28,28,24}
__constant__ int c_TCUM[7] = {0, 12, 32, 58, 86, 114, 138};

__constant__ double c_fact[17] = {
    1.0, 1.0, 2.0, 6.0, 24.0, 120.0, 720.0, 5040.0, 40320.0, 362880.0,
    3628800.0, 39916800.0, 479001600.0, 6227020800.0, 87178291200.0,
    1307674368000.0, 20922789888000.0
};

// ---- packed f32x2 helpers -------------------------------------------------
__device__ __forceinline__ ull ffma2(ull a, ull b, ull c) {
    ull d; asm("fma.rn.f32x2 %0, %1, %2, %3;" : "=l"(d) : "l"(a), "l"(b), "l"(c)); return d;
}
__device__ __forceinline__ float2 upk(ull a) {
    float2 r; asm("mov.b64 {%0,%1}, %2;" : "=f"(r.x), "=f"(r.y) : "l"(a)); return r;
}
#define SGN2 0x8000000080000000ULL

// ---------------------------------------------------------------------------
// Setup kernel: CG coefficients (blocks 0..68) + smem-tiled planar weight
// transpose (blocks 69..206). Tiled transpose: both global streams coalesced.
// ---------------------------------------------------------------------------
__device__ double cg_coeff_d(int l1, int l2, int l, int m1, int m2, int m) {
    double pref = sqrt((2.0 * l + 1.0) * c_fact[l + l1 - l2] * c_fact[l - l1 + l2] *
                       c_fact[l1 + l2 - l] / c_fact[l1 + l2 + l + 1]);
    pref *= sqrt(c_fact[l + m] * c_fact[l - m] * c_fact[l1 - m1] * c_fact[l1 + m1] *
                 c_fact[l2 - m2] * c_fact[l2 + m2]);
    int kmin = 0;
    if (l2 - l - m1 > kmin) kmin = l2 - l - m1;
    if (l1 + m2 - l > kmin) kmin = l1 + m2 - l;
    int kmax = l1 + l2 - l;
    if (l1 - m1 < kmax) kmax = l1 - m1;
    if (l2 + m2 < kmax) kmax = l2 + m2;
    double s = 0.0;
    for (int k = kmin; k <= kmax; k++) {
        double d = c_fact[k] * c_fact[l1 + l2 - l - k] * c_fact[l1 - m1 - k] *
                   c_fact[l2 + m2 - k] * c_fact[l - l2 + m1 + k] * c_fact[l - l1 - m2 + k];
        s += ((k & 1) ? -1.0 : 1.0) / d;
    }
    return pref * s;
}

__global__ void setup_kernel(Meta meta) {
    if (blockIdx.x < NTRIP) {
        int tr = blockIdx.x;
        int l1 = meta.trip_l1[tr], l2 = meta.trip_l2[tr], l = meta.trip_l[tr];
        int off = meta.trip_off[tr];
        int n1 = 2 * l1 + 1, n2 = 2 * l2 + 1;
        int idx = threadIdx.x;
        if (idx >= n1 * n2) return;
        int m1i = idx / n2, m2i = idx % n2;
        int m1 = m1i - l1, m2 = m2i - l2, m = m1 + m2;
        float c = 0.0f;
        if (m >= -l && m <= l)
            c = (float)cg_coeff_d(l1, l2, l, m1, m2, m);
        d_cg[off + idx] = c;
        return;
    }
    // ---- tiled weight transpose: tile = (l, c0..c0+127), all 16 t, both ri
    __shared__ float ts[4096];            // [t][ (c-local, ri) ] = [16][256]
    int tile = blockIdx.x - NTRIP;
    int l = 0;
#pragma unroll
    for (int ll = 1; ll < 6; ll++)
        if (tile >= c_TCUM[ll]) l = ll;
    int c0 = (tile - c_TCUM[l]) * 128;
    int ncols = c_NUMCOLS[l];
    const float* wsrc = meta.w[l];
    int tid = threadIdx.x;
    // coalesced load: 4096 floats; idx = t*256 + (cl*2 + ri); source row t contiguous
#pragma unroll
    for (int k = 0; k < 16; k++) {
        int idx = tid + k * 256;
        int t = idx >> 8;
        int low = idx & 255;              // = cl*2 + ri
        ts[idx] = wsrc[t * ncols * 2 + c0 * 2 + low];
    }
    __syncthreads();
    // coalesced store: dest[plane][WTP[l] + (c0/4 + c4l)*64 + t*4 + j3]
    int dbase = c_WTP[l] + (c0 >> 2) * 64;
#pragma unroll
    for (int k = 0; k < 16; k++) {
        int idx = tid + k * 256;
        int plane = idx >> 11;
        int r = idx & 2047;
        int c4l = r >> 6;
        int rem = r & 63;
        int t = rem >> 2;
        int j3 = rem & 3;
        d_wt[plane * WPLANE + dbase + c4l * 64 + t * 4 + j3] =
            ts[t * 256 + (c4l * 4 + j3) * 2 + plane];
    }
}

// ---------------------------------------------------------------------------
// Stage-2 inner accumulation: 2 accumulator families (real via sign-flipped
// wi), unroll 4 for MLP (R14 champion-tied configuration).
// ---------------------------------------------------------------------------
template <int CNT>
__device__ __forceinline__ void s2_acc(const ulonglong2* __restrict__ wr,
                                       const ulonglong2* __restrict__ wi,
                                       const ulonglong2* __restrict__ fr,
                                       const ulonglong2* __restrict__ fi,
                                       int len, int ooff, float* out_s)
{
    ull A[CNT], C[CNT];
#pragma unroll
    for (int q = 0; q < CNT; q++) { A[q] = 0; C[q] = 0; }
#pragma unroll 4
    for (int p = 0; p < len; p++) {
        ulonglong2 w_r = wr[p * 16];
        ulonglong2 w_i = wi[p * 16];
        ull wnx = w_i.x ^ SGN2;     // -wi (packed sign flip)
        ull wny = w_i.y ^ SGN2;
#pragma unroll
        for (int q = 0; q < CNT; q++) {
            ulonglong2 f_r = fr[q * 64 + p];
            ulonglong2 f_i = fi[q * 64 + p];
            A[q] = ffma2(w_r.x, f_r.x, A[q]);   // real: +wr*fr
            A[q] = ffma2(w_r.y, f_r.y, A[q]);
            A[q] = ffma2(wnx,   f_i.x, A[q]);   // real: -wi*fi
            A[q] = ffma2(wny,   f_i.y, A[q]);
            C[q] = ffma2(w_r.x, f_i.x, C[q]);   // imag: +wr*fi
            C[q] = ffma2(w_r.y, f_i.y, C[q]);
            C[q] = ffma2(w_i.x, f_r.x, C[q]);   // imag: +wi*fr
            C[q] = ffma2(w_i.y, f_r.y, C[q]);
        }
    }
#pragma unroll
    for (int q = 0; q < CNT; q++) {
        float2 a2 = upk(A[q]), c2 = upk(C[q]);
        atomicAdd(&out_s[ooff + 2 * q],     a2.x + a2.y);
        atomicAdd(&out_s[ooff + 2 * q + 1], c2.x + c2.y);
    }
}

// ---------------------------------------------------------------------------
// Stage-2 with in-thread entry decode (no smem lut), cnt-sorted enumeration.
// ---------------------------------------------------------------------------
__device__ __noinline__ void stage2(int E, int LA, int LB, int lcs,
                                    const int* colbase6,
                                    const float* frag_r, const float* frag_i,
                                    float* out_s, int tid)
{
    int csplit = 1 << lcs;
    int cmask = csplit - 1;
    int len = 64 >> lcs;
    int N4 = 0, N3 = 0;
    for (int l = LA; l <= LB; l++) { N4 += l >> 1; N3 += (l & 1); }
    int U4e = N4 * csplit, U3e = N3 * csplit;
    int LA2 = LA * LA;
    for (int e = tid; e < E; e += 256) {
        int t = e & 15;
        int u = e >> 4;
        int l, k0, cnt, ch;
        if (u < U4e) {
            int q = u >> lcs; ch = u & cmask;
            l = LA;
            while (q >= (l >> 1)) { q -= (l >> 1); l++; }
            k0 = q * 4; cnt = 4;
        } else if (u < U4e + U3e) {
            int idx = u - U4e;
            int j = idx >> lcs; ch = idx & cmask;
            l = (LA & 1) ? LA : LA + 1;
            l += 2 * j;
            k0 = (l >> 1) * 4; cnt = 3;
        } else {
            int idx = u - U4e - U3e;
            int j = idx >> lcs; ch = idx & cmask;
            l = (LA & 1) ? LA + 1 : LA;
            l += 2 * j;
            k0 = (l >> 1) * 4; cnt = 1;
        }
        int pstart = ch * len;
        int woff = c_WTP[l] + ((colbase6[l] >> 2) + pstart) * 64 + t * 4;
        int kk0 = (l * l - LA2) + k0;
        int ooff = c_FOFF[l] + (t * (2 * l + 1) + k0) * 2;
        const ulonglong2* wr = (const ulonglong2*)(d_wt + woff);
        const ulonglong2* wi = (const ulonglong2*)(d_wt + WPLANE + woff);
        const ulonglong2* fr = (const ulonglong2*)frag_r + kk0 * 64 + pstart;
        const ulonglong2* fi = (const ulonglong2*)frag_i + kk0 * 64 + pstart;
        if (cnt == 4)      s2_acc<4>(wr, wi, fr, fi, len, ooff, out_s);
        else if (cnt == 3) s2_acc<3>(wr, wi, fr, fi, len, ooff, out_s);
        else               s2_acc<1>(wr, wi, fr, fi, len, ooff, out_s);
    }
}

// ---------------------------------------------------------------------------
// Main fused kernel: one CTA per batch element (R14 champion structure).
// ---------------------------------------------------------------------------
template <int L1, int L2, int LA, int LB>
__device__ __forceinline__ void process_range(
    int g, const Meta& meta, float* __restrict__ f_s, float* __restrict__ out_s,
    const float* __restrict__ cg_a,
    float* __restrict__ frag_r, float* __restrict__ frag_i, int tid)
{
    constexpr int N1 = 2 * L1 + 1;
    constexpr int N2 = 2 * L2 + 1;
    constexpr int STRIDE = N1 * N2;
    constexpr int SK = (LB + 1) * (LB + 1) - LA * LA;
    static_assert(SK <= 21, "frag rows");
    constexpr int KQ =
        (((LA + 0) <= LB) ? ((LA + 0 + 2) / 2) : 0) +
        (((LA + 1) <= LB) ? ((LA + 1 + 2) / 2) : 0) +
        (((LA + 2) <= LB) ? ((LA + 2 + 2) / 2) : 0) +
        (((LA + 3) <= LB) ? ((LA + 3 + 2) / 2) : 0) +
        (((LA + 4) <= LB) ? ((LA + 4 + 2) / 2) : 0) +
        (((LA + 5) <= LB) ? ((LA + 5 + 2) / 2) : 0);
    constexpr int E0 = 16 * KQ;
    constexpr int LCS = (E0 >= 256) ? 0 : ((E0 >= 128) ? 1 : ((E0 >= 64) ? 2 : ((E0 >= 32) ? 3 : 4)));
    constexpr int E = E0 << LCS;

    __syncthreads();  // prior stage2 done reading frag

    // ---- stage 1: CG fragments, thread = (i,j) channel pair = column ----
    {
        int i = tid >> 4, j = tid & 15;
        float accr[SK], acci[SK];
#pragma unroll
        for (int q = 0; q < SK; q++) { accr[q] = 0.0f; acci[q] = 0.0f; }
        const float* cgsub = cg_a + meta.cg_off[g][LA];
        const float* f1 = f_s + c_FOFF[L1] + i * N1 * 2;
        const float* f2 = f_s + c_FOFF[L2] + j * N2 * 2;
#pragma unroll
        for (int m1 = 0; m1 < N1; m1++) {
            float ar = f1[2 * m1], ai = f1[2 * m1 + 1];
#pragma unroll
            for (int m2 = 0; m2 < N2; m2++) {
                float br = f2[2 * m2], bi = f2[2 * m2 + 1];
                float pr = ar * br - ai * bi;
                float pi = ar * bi + ai * br;
                int m = m1 + m2 - L1 - L2;
#pragma unroll
                for (int l = LA; l <= LB; l++) {
                    if (m >= -l && m <= l) {
                        float c = cgsub[(l - LA) * STRIDE + m1 * N2 + m2];
                        int kk = (l * l - LA * LA) + m + l;
                        accr[kk] += c * pr;
                        acci[kk] += c * pi;
                    }
                }
            }
        }
#pragma unroll
        for (int q = 0; q < SK; q++) {
            frag_r[q * 256 + tid] = accr[q];
            frag_i[q * 256 + tid] = acci[q];
        }
    }
    __syncthreads();  // fragments ready

    stage2(E, LA, LB, LCS, meta.col_base[g], frag_r, frag_i, out_s, tid);
}

__global__ void __launch_bounds__(256, 2) uf_kernel(Meta meta) {
    extern __shared__ float smem[];
    float* f_s    = smem;                 // 1152
    float* out_s  = smem + 1152;          // 1152
    float* cg_a   = smem + 2304;          // 4096 (4066 used), resident CG table
    float* frag_r = smem + 6400;          // 5376 (21 rows * 256), 16B-aligned
    float* frag_i = smem + 11776;         // 5376   total 17152 words = 68608 B

    int tid = threadIdx.x;
    int b = blockIdx.x;

#pragma unroll
    for (int l = 0; l < 6; l++) {
        int n = 32 * (2 * l + 1);
        const float* src = meta.f[l] + b * n;
        for (int s = tid; s < n; s += 256) f_s[c_FOFF[l] + s] = src[s];
    }
    for (int s = tid; s < 1152; s += 256) out_s[s] = 0.0f;
    for (int s = tid; s < NCG; s += 256) cg_a[s] = d_cg[s];

#define PG(A, B2, G, LA, LB) \
    process_range<A, B2, LA, LB>(G, meta, f_s, out_s, cg_a, frag_r, frag_i, tid)
    PG(0, 0, 0, 0, 0);
    PG(1, 0, 1, 1, 1);
    PG(1, 1, 2, 0, 2);
    PG(2, 0, 3, 2, 2);
    PG(2, 1, 4, 1, 3);
    PG(2, 2, 5, 0, 3);  PG(2, 2, 5, 4, 4);
    PG(3, 0, 6, 3, 3);
    PG(3, 1, 7, 2, 4);
    PG(3, 2, 8, 1, 3);  PG(3, 2, 8, 4, 5);
    PG(3, 3, 9, 0, 3);  PG(3, 3, 9, 4, 5);
    PG(4, 0, 10, 4, 4);
    PG(4, 1, 11, 3, 4); PG(4, 1, 11, 5, 5);
    PG(4, 2, 12, 2, 4); PG(4, 2, 12, 5, 5);
    PG(4, 3, 13, 1, 3); PG(4, 3, 13, 4, 5);
    PG(4, 4, 14, 0, 3); PG(4, 4, 14, 4, 5);
    PG(5, 0, 15, 5, 5);
    PG(5, 1, 16, 4, 5);
    PG(5, 2, 17, 3, 4); PG(5, 2, 17, 5, 5);
    PG(5, 3, 18, 2, 4); PG(5, 3, 18, 5, 5);
    PG(5, 4, 19, 1, 3); PG(5, 4, 19, 4, 5);
    PG(5, 5, 20, 0, 3); PG(5, 5, 20, 4, 5);
#undef PG

    __syncthreads();
    for (int s = tid; s < 1152; s += 256) {
        int l = 0;
#pragma unroll
        for (int ll = 1; ll < 6; ll++)
            if (s >= c_FOFF[ll]) l = ll;
        int rel = s - c_FOFF[l];
        meta.out[c_OUTOFF[l] + b * 32 * (2 * l + 1) + rel] = out_s[s];
    }
}

// ---------------------------------------------------------------------------
// Host launch
// ---------------------------------------------------------------------------
extern "C" void kernel_launch(void* const* d_in, const int* in_sizes, int n_in,
                              void* d_out, int out_size) {
    Meta m;
    const int fsz[6] = {8192, 24576, 40960, 57344, 73728, 90112};
    const int wsz[6] = {49152, 81920, 106496, 114688, 114688, 98304};
    bool used[64];
    for (int i = 0; i < 64; i++) used[i] = false;
    for (int l = 0; l < 6; l++) {
        for (int idx = 0; idx < n_in; idx++) {
            if (!used[idx] && in_sizes[idx] == fsz[l]) {
                m.f[l] = (const float*)d_in[idx];
                used[idx] = true;
                break;
            }
        }
    }
    for (int l = 0; l < 6; l++) {
        for (int idx = 0; idx < n_in; idx++) {
            if (!used[idx] && in_sizes[idx] == wsz[l]) {
                m.w[l] = (const float*)d_in[idx];
                used[idx] = true;
                break;
            }
        }
    }
    m.out = (float*)d_out;

    int off = 0, g = 0, tr = 0;
    int cnt[6] = {0, 0, 0, 0, 0, 0};
    for (int l1 = 0; l1 <= 5; l1++) {
        for (int l2 = 0; l2 <= l1; l2++) {
            int lmin = l1 - l2;
            int lmax = (l1 + l2 < 5) ? (l1 + l2) : 5;
            for (int l = lmin; l <= lmax; l++) {
                m.cg_off[g][l] = off;
                m.trip_l1[tr] = l1;
                m.trip_l2[tr] = l2;
                m.trip_l[tr]  = l;
                m.trip_off[tr] = off;
                tr++;
                off += (2 * l1 + 1) * (2 * l2 + 1);
                m.col_base[g][l] = cnt[l] * 256;
                cnt[l]++;
            }
            g++;
        }
    }

    const int SMEM_BYTES = 17152 * 4;  // 68608
    cudaFuncSetAttribute(uf_kernel, cudaFuncAttributeMaxDynamicSharedMemorySize, SMEM_BYTES);

    setup_kernel<<<NTRIP + NTILE, 256>>>(m);
    uf_kernel<<<256, 256, SMEM_BYTES>>>(m);
}